// round 16
// baseline (speedup 1.0000x reference)
#include <cuda_runtime.h>
#include <cuda_bf16.h>
#include <math.h>

// ---------------------------------------------------------------------------
// Problem constants
// ---------------------------------------------------------------------------
#define BB  32
#define PP  512
#define NN  512
#define EMB 256
#define HH  16
#define DD  16

// Scratch (device globals -- no allocation allowed)
__device__ float g_K[BB * HH * NN * DD];    // [b][h][n][d]
__device__ float g_V[BB * HH * NN * DD];    // [b][h][n][d]
__device__ float g_Q[BB * HH * PP * DD];    // [b][h][p][d]
__device__ float g_att[BB * PP * HH * DD];  // [b][p][h*16+d]
__device__ float g_mh[BB * PP * EMB];       // [b][p][e]
__device__ int   g_mask_nz;                 // 1 if any ninf_mask bit set

// ---------------------------------------------------------------------------
// mma.sync m16n8k16 bf16 + ldmatrix helpers
// ---------------------------------------------------------------------------
__device__ __forceinline__ void mma16816(float* c, const unsigned* a, const unsigned* b) {
    asm volatile(
        "mma.sync.aligned.m16n8k16.row.col.f32.bf16.bf16.f32 "
        "{%0,%1,%2,%3}, {%4,%5,%6,%7}, {%8,%9}, {%0,%1,%2,%3};"
        : "+f"(c[0]), "+f"(c[1]), "+f"(c[2]), "+f"(c[3])
        : "r"(a[0]), "r"(a[1]), "r"(a[2]), "r"(a[3]), "r"(b[0]), "r"(b[1]));
}

__device__ __forceinline__ void ldsm_x4(unsigned& d0, unsigned& d1,
                                        unsigned& d2, unsigned& d3, unsigned addr) {
    asm volatile("ldmatrix.sync.aligned.m8n8.x4.shared.b16 {%0,%1,%2,%3}, [%4];"
                 : "=r"(d0), "=r"(d1), "=r"(d2), "=r"(d3) : "r"(addr));
}

__device__ __forceinline__ unsigned pack_bf16x2(float lo, float hi) {
    unsigned r;
    asm("cvt.rn.satfinite.bf16x2.f32 %0, %1, %2;" : "=r"(r) : "f"(hi), "f"(lo));
    return r;
}

__device__ __forceinline__ void pack_hl(float x0, float x1, unsigned& ph, unsigned& pl) {
    ph = pack_bf16x2(x0, x1);
    const float h0 = __uint_as_float(ph << 16);
    const float h1 = __uint_as_float(ph & 0xFFFF0000u);
    pl = pack_bf16x2(x0 - h0, x1 - h1);
}

__device__ __forceinline__ void cvt_hl(float x, __nv_bfloat16& h, __nv_bfloat16& l) {
    h = __float2bfloat16(x);
    l = __float2bfloat16(x - __bfloat162float(h));
}

__device__ __forceinline__ void store_hl4(__nv_bfloat16* p_h, __nv_bfloat16* p_l, float4 v) {
    unsigned h01, l01, h23, l23;
    pack_hl(v.x, v.y, h01, l01);
    pack_hl(v.z, v.w, h23, l23);
    *(unsigned*)(p_h)     = h01;
    *(unsigned*)(p_h + 2) = h23;
    *(unsigned*)(p_l)     = l01;
    *(unsigned*)(p_l + 2) = l23;
}

#define LDAB 40  // padded bf16 row stride (80 B) -> LDSM conflict-free

// Pipelined GEMM stage layout (elements)
#define P_AH   0
#define P_AL   (128 * LDAB)
#define P_BH   (256 * LDAB)
#define P_BL   (256 * LDAB + 64 * LDAB)
#define P_STAGE (384 * LDAB)   // 15360 elems = 30720 B per stage

// ---------------------------------------------------------------------------
// Flag init
// ---------------------------------------------------------------------------
__global__ void init_flag_kernel() {
    if (threadIdx.x == 0) g_mask_nz = 0;
}

// ---------------------------------------------------------------------------
// Merged projection kernel (pipelined, double-buffered smem).
// blockIdx.z selects K / V / Q; mask OR-scan spread over ALL blocks.
// ---------------------------------------------------------------------------
__global__ __launch_bounds__(256, 2) void proj_kernel(
    const float* __restrict__ enc,
    const float* __restrict__ last,
    const float* __restrict__ loadv,
    const float* __restrict__ Wk,
    const float* __restrict__ Wv,
    const float* __restrict__ Wq,
    const float* __restrict__ mask)
{
    extern __shared__ __nv_bfloat16 smp[];
    __shared__ unsigned sred[8];

    const int z = blockIdx.z;
    const float* Ap = (z == 2) ? last : enc;
    const float* W  = (z == 0) ? Wk : (z == 1) ? Wv : Wq;
    const int ldw   = (z == 2) ? 257 : 256;
    const bool extra = (z == 2);
    float* out = (z == 0) ? g_K : (z == 1) ? g_V : g_Q;

    const int m0 = blockIdx.x * 128;
    const int n0 = blockIdx.y * 64;
    const int tid = threadIdx.x;
    const int warp = tid >> 5, lane = tid & 31;
    const int wm = warp >> 1, wn = warp & 1;
    const int gr = lane >> 2, qc = lane & 3;
    const int lt = lane >> 3, lr = lane & 7;

    // ---- mask OR-scan (spread across all 1536 blocks) ----
    {
        unsigned accm = 0;
        const unsigned bid = blockIdx.z * 512u + blockIdx.y * 128u + blockIdx.x;
        const uint4* m4 = (const uint4*)mask;
        for (unsigned i = bid * 256u + tid; i < 2097152u; i += 1536u * 256u) {
            uint4 v = m4[i];
            accm |= v.x | v.y | v.z | v.w;
        }
#pragma unroll
        for (int o = 16; o; o >>= 1) accm |= __shfl_xor_sync(0xffffffffu, accm, o);
        if (lane == 0) sred[warp] = accm;
        __syncthreads();
        if (tid == 0) {
            unsigned a = 0;
#pragma unroll
            for (int i = 0; i < 8; i++) a |= sred[i];
            if (a) atomicOr(&g_mask_nz, 1);
        }
    }

    const unsigned sb = (unsigned)__cvta_generic_to_shared(smp);
    const unsigned aH0 = sb + (P_AH + (wm * 32 + (lt & 1) * 8 + lr) * LDAB + (lt >> 1) * 8) * 2;
    const unsigned aL0 = sb + (P_AL + (wm * 32 + (lt & 1) * 8 + lr) * LDAB + (lt >> 1) * 8) * 2;
    const unsigned bH0 = sb + (P_BH + (wn * 32 + (lt >> 1) * 8 + lr) * LDAB + (lt & 1) * 8) * 2;
    const unsigned bL0 = sb + (P_BL + (wn * 32 + (lt >> 1) * 8 + lr) * LDAB + (lt & 1) * 8) * 2;

    float acc[2][4][4];
#pragma unroll
    for (int mt = 0; mt < 2; mt++)
#pragma unroll
        for (int nt = 0; nt < 4; nt++)
#pragma unroll
            for (int e = 0; e < 4; e++) acc[mt][nt][e] = 0.0f;

    float4 av[4];
    float wv[2][4];
#pragma unroll
    for (int i = 0; i < 4; i++) {
        const int lin = tid + i * 256;
        const int row = lin >> 3, c4 = lin & 7;
        av[i] = *(const float4*)(Ap + (size_t)(m0 + row) * 256 + c4 * 4);
    }
#pragma unroll
    for (int i = 0; i < 2; i++) {
        const int lin = tid + i * 256;
        const int row = lin >> 3, c4 = lin & 7;
        const float* wp = W + (size_t)(n0 + row) * ldw + c4 * 4;
        if (extra) {
            wv[i][0] = wp[0]; wv[i][1] = wp[1]; wv[i][2] = wp[2]; wv[i][3] = wp[3];
        } else {
            float4 t = *(const float4*)wp;
            wv[i][0] = t.x; wv[i][1] = t.y; wv[i][2] = t.z; wv[i][3] = t.w;
        }
    }

#pragma unroll 1
    for (int kb = 0; kb < 8; kb++) {
        const int bufo = (kb & 1) * P_STAGE;
        __nv_bfloat16* Ah = smp + bufo + P_AH;
        __nv_bfloat16* Al = smp + bufo + P_AL;
        __nv_bfloat16* Bh = smp + bufo + P_BH;
        __nv_bfloat16* Bl = smp + bufo + P_BL;
#pragma unroll
        for (int i = 0; i < 4; i++) {
            const int lin = tid + i * 256;
            const int row = lin >> 3, c4 = lin & 7;
            store_hl4(&Ah[row * LDAB + c4 * 4], &Al[row * LDAB + c4 * 4], av[i]);
        }
#pragma unroll
        for (int i = 0; i < 2; i++) {
            const int lin = tid + i * 256;
            const int row = lin >> 3, c4 = lin & 7;
            float4 t = make_float4(wv[i][0], wv[i][1], wv[i][2], wv[i][3]);
            store_hl4(&Bh[row * LDAB + c4 * 4], &Bl[row * LDAB + c4 * 4], t);
        }
        __syncthreads();

        if (kb < 7) {
            const int k0 = (kb + 1) * 32;
#pragma unroll
            for (int i = 0; i < 4; i++) {
                const int lin = tid + i * 256;
                const int row = lin >> 3, c4 = lin & 7;
                av[i] = *(const float4*)(Ap + (size_t)(m0 + row) * 256 + k0 + c4 * 4);
            }
#pragma unroll
            for (int i = 0; i < 2; i++) {
                const int lin = tid + i * 256;
                const int row = lin >> 3, c4 = lin & 7;
                const float* wp = W + (size_t)(n0 + row) * ldw + k0 + c4 * 4;
                if (extra) {
                    wv[i][0] = wp[0]; wv[i][1] = wp[1]; wv[i][2] = wp[2]; wv[i][3] = wp[3];
                } else {
                    float4 t = *(const float4*)wp;
                    wv[i][0] = t.x; wv[i][1] = t.y; wv[i][2] = t.z; wv[i][3] = t.w;
                }
            }
        }

        const unsigned bo2 = bufo * 2;
#pragma unroll
        for (int ks = 0; ks < 32; ks += 16) {
            unsigned ah[2][4], al[2][4], bh[4][2], bl[4][2];
#pragma unroll
            for (int mt = 0; mt < 2; mt++) {
                ldsm_x4(ah[mt][0], ah[mt][1], ah[mt][2], ah[mt][3],
                        aH0 + bo2 + (mt * 16 * LDAB + ks) * 2);
                ldsm_x4(al[mt][0], al[mt][1], al[mt][2], al[mt][3],
                        aL0 + bo2 + (mt * 16 * LDAB + ks) * 2);
            }
#pragma unroll
            for (int p = 0; p < 2; p++) {
                ldsm_x4(bh[2 * p][0], bh[2 * p][1], bh[2 * p + 1][0], bh[2 * p + 1][1],
                        bH0 + bo2 + (p * 16 * LDAB + ks) * 2);
                ldsm_x4(bl[2 * p][0], bl[2 * p][1], bl[2 * p + 1][0], bl[2 * p + 1][1],
                        bL0 + bo2 + (p * 16 * LDAB + ks) * 2);
            }
#pragma unroll
            for (int mt = 0; mt < 2; mt++)
#pragma unroll
                for (int nt = 0; nt < 4; nt++) {
                    mma16816(acc[mt][nt], ah[mt], bh[nt]);
                    mma16816(acc[mt][nt], ah[mt], bl[nt]);
                    mma16816(acc[mt][nt], al[mt], bh[nt]);
                }
        }
    }

#pragma unroll
    for (int mt = 0; mt < 2; mt++) {
#pragma unroll
        for (int part = 0; part < 2; part++) {
            const int m = m0 + wm * 32 + mt * 16 + gr + part * 8;
            float ex = 0.0f;
            if (extra) ex = loadv[m];
#pragma unroll
            for (int nt = 0; nt < 4; nt++) {
                const int col = n0 + wn * 32 + nt * 8 + 2 * qc;
                float2 v = make_float2(acc[mt][nt][part * 2], acc[mt][nt][part * 2 + 1]);
                if (extra) {
                    v.x += ex * W[(size_t)col * ldw + 256];
                    v.y += ex * W[(size_t)(col + 1) * ldw + 256];
                }
                const int b = m >> 9, n = m & 511;
                const int h = col >> 4, d = col & 15;
                *(float2*)&out[(((size_t)(b * 16 + h) * 512) + n) * 16 + d] = v;
            }
        }
    }
}

// ---------------------------------------------------------------------------
// Wc projection (pipelined, double-buffered): g_att @ Wc^T + bias -> g_mh
// ---------------------------------------------------------------------------
__global__ __launch_bounds__(256, 2) void gemm_wc_kernel(
    const float* __restrict__ W,
    const float* __restrict__ bias)
{
    extern __shared__ __nv_bfloat16 smp[];
    const float* Ap = (const float*)g_att;
    float* out = g_mh;

    const int m0 = blockIdx.x * 128;
    const int n0 = blockIdx.y * 64;
    const int tid = threadIdx.x;
    const int warp = tid >> 5, lane = tid & 31;
    const int wm = warp >> 1, wn = warp & 1;
    const int gr = lane >> 2, qc = lane & 3;
    const int lt = lane >> 3, lr = lane & 7;

    const unsigned sb = (unsigned)__cvta_generic_to_shared(smp);
    const unsigned aH0 = sb + (P_AH + (wm * 32 + (lt & 1) * 8 + lr) * LDAB + (lt >> 1) * 8) * 2;
    const unsigned aL0 = sb + (P_AL + (wm * 32 + (lt & 1) * 8 + lr) * LDAB + (lt >> 1) * 8) * 2;
    const unsigned bH0 = sb + (P_BH + (wn * 32 + (lt >> 1) * 8 + lr) * LDAB + (lt & 1) * 8) * 2;
    const unsigned bL0 = sb + (P_BL + (wn * 32 + (lt >> 1) * 8 + lr) * LDAB + (lt & 1) * 8) * 2;

    float acc[2][4][4];
#pragma unroll
    for (int mt = 0; mt < 2; mt++)
#pragma unroll
        for (int nt = 0; nt < 4; nt++)
#pragma unroll
            for (int e = 0; e < 4; e++) acc[mt][nt][e] = 0.0f;

    float4 av[4], wv[2];
#pragma unroll
    for (int i = 0; i < 4; i++) {
        const int lin = tid + i * 256;
        const int row = lin >> 3, c4 = lin & 7;
        av[i] = *(const float4*)(Ap + (size_t)(m0 + row) * 256 + c4 * 4);
    }
#pragma unroll
    for (int i = 0; i < 2; i++) {
        const int lin = tid + i * 256;
        const int row = lin >> 3, c4 = lin & 7;
        wv[i] = *(const float4*)(W + (size_t)(n0 + row) * 256 + c4 * 4);
    }

#pragma unroll 1
    for (int kb = 0; kb < 8; kb++) {
        const int bufo = (kb & 1) * P_STAGE;
        __nv_bfloat16* Ah = smp + bufo + P_AH;
        __nv_bfloat16* Al = smp + bufo + P_AL;
        __nv_bfloat16* Bh = smp + bufo + P_BH;
        __nv_bfloat16* Bl = smp + bufo + P_BL;
#pragma unroll
        for (int i = 0; i < 4; i++) {
            const int lin = tid + i * 256;
            const int row = lin >> 3, c4 = lin & 7;
            store_hl4(&Ah[row * LDAB + c4 * 4], &Al[row * LDAB + c4 * 4], av[i]);
        }
#pragma unroll
        for (int i = 0; i < 2; i++) {
            const int lin = tid + i * 256;
            const int row = lin >> 3, c4 = lin & 7;
            store_hl4(&Bh[row * LDAB + c4 * 4], &Bl[row * LDAB + c4 * 4], wv[i]);
        }
        __syncthreads();

        if (kb < 7) {
            const int k0 = (kb + 1) * 32;
#pragma unroll
            for (int i = 0; i < 4; i++) {
                const int lin = tid + i * 256;
                const int row = lin >> 3, c4 = lin & 7;
                av[i] = *(const float4*)(Ap + (size_t)(m0 + row) * 256 + k0 + c4 * 4);
            }
#pragma unroll
            for (int i = 0; i < 2; i++) {
                const int lin = tid + i * 256;
                const int row = lin >> 3, c4 = lin & 7;
                wv[i] = *(const float4*)(W + (size_t)(n0 + row) * 256 + k0 + c4 * 4);
            }
        }

        const unsigned bo2 = bufo * 2;
#pragma unroll
        for (int ks = 0; ks < 32; ks += 16) {
            unsigned ah[2][4], al[2][4], bh[4][2], bl[4][2];
#pragma unroll
            for (int mt = 0; mt < 2; mt++) {
                ldsm_x4(ah[mt][0], ah[mt][1], ah[mt][2], ah[mt][3],
                        aH0 + bo2 + (mt * 16 * LDAB + ks) * 2);
                ldsm_x4(al[mt][0], al[mt][1], al[mt][2], al[mt][3],
                        aL0 + bo2 + (mt * 16 * LDAB + ks) * 2);
            }
#pragma unroll
            for (int p = 0; p < 2; p++) {
                ldsm_x4(bh[2 * p][0], bh[2 * p][1], bh[2 * p + 1][0], bh[2 * p + 1][1],
                        bH0 + bo2 + (p * 16 * LDAB + ks) * 2);
                ldsm_x4(bl[2 * p][0], bl[2 * p][1], bl[2 * p + 1][0], bl[2 * p + 1][1],
                        bL0 + bo2 + (p * 16 * LDAB + ks) * 2);
            }
#pragma unroll
            for (int mt = 0; mt < 2; mt++)
#pragma unroll
                for (int nt = 0; nt < 4; nt++) {
                    mma16816(acc[mt][nt], ah[mt], bh[nt]);
                    mma16816(acc[mt][nt], ah[mt], bl[nt]);
                    mma16816(acc[mt][nt], al[mt], bh[nt]);
                }
        }
    }

#pragma unroll
    for (int mt = 0; mt < 2; mt++) {
#pragma unroll
        for (int part = 0; part < 2; part++) {
            const int m = m0 + wm * 32 + mt * 16 + gr + part * 8;
#pragma unroll
            for (int nt = 0; nt < 4; nt++) {
                const int col = n0 + wn * 32 + nt * 8 + 2 * qc;
                float2 v = make_float2(acc[mt][nt][part * 2], acc[mt][nt][part * 2 + 1]);
                v.x += bias[col]; v.y += bias[col + 1];
                *(float2*)&out[(size_t)m * 256 + col] = v;
            }
        }
    }
}

// ---------------------------------------------------------------------------
// Flash attention v11: 4 p-tiles per block (K/V staged once for the full
// (b,h)); Q fragments direct from gmem; LDSM K/V; mask-skip.
// ---------------------------------------------------------------------------
#define KH_LD 24
#define VT_LD 520
#define A6_KH   0
#define A6_KL   (512 * KH_LD)
#define A6_VTH  (2 * 512 * KH_LD)
#define A6_VTL  (A6_VTH + 16 * VT_LD)
#define A6_TOT  (A6_VTL + 16 * VT_LD)   // 41216 elems = 82432 B

__global__ __launch_bounds__(256, 2) void attention11_kernel(
    const float* __restrict__ mask)
{
    extern __shared__ __nv_bfloat16 smb[];
    __nv_bfloat16* Kh  = smb + A6_KH;
    __nv_bfloat16* Kl  = smb + A6_KL;
    __nv_bfloat16* Vth = smb + A6_VTH;
    __nv_bfloat16* Vtl = smb + A6_VTL;

    const int bh = blockIdx.x;
    const int b  = bh >> 4;
    const int h  = bh & 15;
    const int tid = threadIdx.x;
    const int anymask = g_mask_nz;

    // ---- stage K/V once per block (serves all 4 p-tiles) ----
    const float4* Kg4 = (const float4*)(g_K + (size_t)bh * (NN * DD));
    for (int i = tid; i < 2048; i += 256) {
        float4 v = Kg4[i];
        const int row = i >> 2, dg = (i & 3) * 4;
        store_hl4(&Kh[row * KH_LD + dg], &Kl[row * KH_LD + dg], v);
    }
    const float4* Vg4 = (const float4*)(g_V + (size_t)bh * (NN * DD));
    for (int i = tid; i < 2048; i += 256) {
        float4 v = Vg4[i];
        const int n = i >> 2, dg = (i & 3) * 4;
        float x[4] = {v.x, v.y, v.z, v.w};
#pragma unroll
        for (int j = 0; j < 4; j++) {
            __nv_bfloat16 hh, ll;
            cvt_hl(x[j], hh, ll);
            Vth[(dg + j) * VT_LD + n] = hh;
            Vtl[(dg + j) * VT_LD + n] = ll;
        }
    }
    __syncthreads();

    const int warp = tid >> 5, lane = tid & 31;
    const int gr = lane >> 2, qc = lane & 3;
    const int lt = lane >> 3, lr = lane & 7;
    const int prow = warp * 16;

    const unsigned sb = (unsigned)__cvta_generic_to_shared(smb);
    const unsigned kBase = sb + ((lt < 2 ? A6_KH : A6_KL)
                                 + lr * KH_LD + (lt & 1) * 8) * 2;
    const unsigned vBase = sb + ((lt < 2 ? A6_VTH : A6_VTL)
                                 + lr * VT_LD + (lt & 1) * 8) * 2;

#pragma unroll 1
    for (int ip = 0; ip < 4; ip++) {
        const int p0 = ip * 128;

        // ---- Q fragments: direct gmem loads ----
        unsigned qh[4], ql[4];
        {
            const float2* q0 = (const float2*)(g_Q + ((size_t)bh * PP + p0 + prow + gr) * DD);
            const float2* q1 = (const float2*)(g_Q + ((size_t)bh * PP + p0 + prow + gr + 8) * DD);
            float2 a = q0[qc], bq = q1[qc], cq = q0[qc + 4], d = q1[qc + 4];
            pack_hl(a.x * 0.25f,  a.y * 0.25f,  qh[0], ql[0]);
            pack_hl(bq.x * 0.25f, bq.y * 0.25f, qh[1], ql[1]);
            pack_hl(cq.x * 0.25f, cq.y * 0.25f, qh[2], ql[2]);
            pack_hl(d.x * 0.25f,  d.y * 0.25f,  qh[3], ql[3]);
        }

        float m0 = -1e30f, m1 = -1e30f, l0 = 0.0f, l1 = 0.0f;
        float O[2][4];
#pragma unroll
        for (int nd = 0; nd < 2; nd++)
#pragma unroll
            for (int e = 0; e < 4; e++) O[nd][e] = 0.0f;

        const size_t mrow0 = ((size_t)(b * PP + p0 + prow + gr)) * NN;
        const size_t mrow1 = ((size_t)(b * PP + p0 + prow + gr + 8)) * NN;

#pragma unroll 1
        for (int c = 0; c < 8; c++) {
            const int n0c = c * 64;

            float s[8][4];
#pragma unroll
            for (int nf = 0; nf < 8; nf++) {
                s[nf][0] = s[nf][1] = s[nf][2] = s[nf][3] = 0.0f;
                unsigned kbh[2], kbl[2];
                ldsm_x4(kbh[0], kbh[1], kbl[0], kbl[1],
                        kBase + (n0c + nf * 8) * (KH_LD * 2));
                mma16816(s[nf], qh, kbh);
                mma16816(s[nf], qh, kbl);
                mma16816(s[nf], ql, kbh);
            }

            if (anymask) {
#pragma unroll
                for (int nf = 0; nf < 8; nf++) {
                    const int ncol = n0c + nf * 8 + 2 * qc;
                    float2 mk0 = *(const float2*)&mask[mrow0 + ncol];
                    float2 mk1 = *(const float2*)&mask[mrow1 + ncol];
                    s[nf][0] += mk0.x; s[nf][1] += mk0.y;
                    s[nf][2] += mk1.x; s[nf][3] += mk1.y;
                }
            }

            float mx0 = -1e30f, mx1 = -1e30f;
#pragma unroll
            for (int nf = 0; nf < 8; nf++) {
                mx0 = fmaxf(mx0, fmaxf(s[nf][0], s[nf][1]));
                mx1 = fmaxf(mx1, fmaxf(s[nf][2], s[nf][3]));
            }
            mx0 = fmaxf(mx0, __shfl_xor_sync(0xffffffffu, mx0, 1));
            mx0 = fmaxf(mx0, __shfl_xor_sync(0xffffffffu, mx0, 2));
            mx1 = fmaxf(mx1, __shfl_xor_sync(0xffffffffu, mx1, 1));
            mx1 = fmaxf(mx1, __shfl_xor_sync(0xffffffffu, mx1, 2));

            const float mn0 = fmaxf(m0, mx0);
            const float mn1 = fmaxf(m1, mx1);
            const float f0 = __expf(m0 - mn0);
            const float f1 = __expf(m1 - mn1);
            m0 = mn0; m1 = mn1;
#pragma unroll
            for (int nd = 0; nd < 2; nd++) {
                O[nd][0] *= f0; O[nd][1] *= f0;
                O[nd][2] *= f1; O[nd][3] *= f1;
            }

            float rs0 = 0.0f, rs1 = 0.0f;
#pragma unroll
            for (int nf = 0; nf < 8; nf++) {
                s[nf][0] = __expf(s[nf][0] - mn0);
                s[nf][1] = __expf(s[nf][1] - mn0);
                s[nf][2] = __expf(s[nf][2] - mn1);
                s[nf][3] = __expf(s[nf][3] - mn1);
                rs0 += s[nf][0] + s[nf][1];
                rs1 += s[nf][2] + s[nf][3];
            }
            rs0 += __shfl_xor_sync(0xffffffffu, rs0, 1);
            rs0 += __shfl_xor_sync(0xffffffffu, rs0, 2);
            rs1 += __shfl_xor_sync(0xffffffffu, rs1, 1);
            rs1 += __shfl_xor_sync(0xffffffffu, rs1, 2);
            l0 = l0 * f0 + rs0;
            l1 = l1 * f1 + rs1;

#pragma unroll
            for (int t = 0; t < 4; t++) {
                unsigned ah[4], al[4];
                pack_hl(s[2 * t][0],     s[2 * t][1],     ah[0], al[0]);
                pack_hl(s[2 * t][2],     s[2 * t][3],     ah[1], al[1]);
                pack_hl(s[2 * t + 1][0], s[2 * t + 1][1], ah[2], al[2]);
                pack_hl(s[2 * t + 1][2], s[2 * t + 1][3], ah[3], al[3]);
#pragma unroll
                for (int nd = 0; nd < 2; nd++) {
                    unsigned vbh[2], vbl[2];
                    ldsm_x4(vbh[0], vbh[1], vbl[0], vbl[1],
                            vBase + (nd * 8 * VT_LD + n0c + 16 * t) * 2);
                    mma16816(O[nd], ah, vbh);
                    mma16816(O[nd], ah, vbl);
                    mma16816(O[nd], al, vbh);
                }
            }
        }

        const float inv0 = 1.0f / l0;
        const float inv1 = 1.0f / l1;
        float* op0 = g_att + ((size_t)(b * PP + p0 + prow + gr)) * (HH * DD) + h * DD;
        float* op1 = g_att + ((size_t)(b * PP + p0 + prow + gr + 8)) * (HH * DD) + h * DD;
#pragma unroll
        for (int nd = 0; nd < 2; nd++) {
            *(float2*)&op0[nd * 8 + 2 * qc] = make_float2(O[nd][0] * inv0, O[nd][1] * inv0);
            *(float2*)&op1[nd * 8 + 2 * qc] = make_float2(O[nd][2] * inv1, O[nd][3] * inv1);
        }
    }
}

// ---------------------------------------------------------------------------
// Final fused kernel v7b: tau-first (2-way interleaved search), A staged once,
// B k-pipelined, fixed softmax shift 10, unnormalized exp -> out, rescale.
// ---------------------------------------------------------------------------
#define F_BH 0
#define F_BL (128 * LDAB)
#define F_BSTAGE (256 * LDAB)
#define F_AH (2 * F_BSTAGE)
#define F_A_LD 264
#define F_AL (F_AH + 32 * F_A_LD)
#define F_TOT (F_AL + 32 * F_A_LD)

__global__ __launch_bounds__(256, 2) void final7_kernel(
    const float* __restrict__ enc,
    const float* __restrict__ dist,
    const float* __restrict__ mask,
    float* __restrict__ out)
{
    extern __shared__ __nv_bfloat16 smf[];
    __shared__ float s_tau[32];
    __shared__ float s_sum[32];

    const int b = blockIdx.y;
    const int p0 = blockIdx.x * 32;
    const int tid = threadIdx.x;
    const int warp = tid >> 5, lane = tid & 31;
    const int wm = warp >> 2, wn = warp & 3;
    const int gr = lane >> 2, qc = lane & 3;
    const int lt = lane >> 3, lr = lane & 7;
    const int anymask = g_mask_nz;

    if (tid < 32) s_sum[tid] = 0.0f;

    // ---- phase A: per-row tau, 2 searches interleaved ----
#pragma unroll 1
    for (int rp = 0; rp < 2; rp++) {
        const int r0 = warp * 4 + rp * 2;
        unsigned key[2][16];
#pragma unroll
        for (int rr = 0; rr < 2; rr++) {
            const float* drow = dist + ((size_t)(b * PP + p0 + r0 + rr)) * NN;
#pragma unroll
            for (int j = 0; j < 16; j++) {
                unsigned u = __float_as_uint(drow[j * 32 + lane]);
                key[rr][j] = (u & 0x80000000u) ? ~u : (u ^ 0x80000000u);
            }
        }
        unsigned lo[2] = {0u, 0u}, hi[2] = {0xffffffffu, 0xffffffffu};
#pragma unroll 1
        for (int it = 0; it < 32; it++) {
            unsigned mid[2]; int c[2];
#pragma unroll
            for (int rr = 0; rr < 2; rr++) {
                mid[rr] = lo[rr] + ((hi[rr] - lo[rr]) >> 1);
                int cc = 0;
#pragma unroll
                for (int j = 0; j < 16; j++) cc += (key[rr][j] <= mid[rr]) ? 1 : 0;
                c[rr] = cc;
            }
            c[0] = __reduce_add_sync(0xffffffffu, c[0]);
            c[1] = __reduce_add_sync(0xffffffffu, c[1]);
#pragma unroll
            for (int rr = 0; rr < 2; rr++) {
                if (c[rr] >= 100) hi[rr] = mid[rr]; else lo[rr] = mid[rr] + 1;
            }
        }
        if (lane == 0) {
#pragma unroll
            for (int rr = 0; rr < 2; rr++) {
                const unsigned tau = hi[rr];
                const unsigned u = (tau & 0x80000000u) ? (tau ^ 0x80000000u) : ~tau;
                s_tau[r0 + rr] = __uint_as_float(u);
            }
        }
    }

    // ---- stage A (mh tile, FULL K) once ----
    __nv_bfloat16* Ah = smf + F_AH;
    __nv_bfloat16* Al = smf + F_AL;
#pragma unroll
    for (int i = 0; i < 8; i++) {
        const int lin = tid + i * 256;
        const int row = lin >> 6, c4 = lin & 63;
        float4 av = *(const float4*)&g_mh[((size_t)(b * PP + p0 + row)) * 256 + c4 * 4];
        store_hl4(&Ah[row * F_A_LD + c4 * 4], &Al[row * F_A_LD + c4 * 4], av);
    }
    __syncthreads();

    const unsigned sb = (unsigned)__cvta_generic_to_shared(smf);
    const unsigned aHb = sb + (F_AH + (wm * 16 + (lt & 1) * 8 + lr) * F_A_LD + (lt >> 1) * 8) * 2;
    const unsigned aLb = sb + (F_AL + (wm * 16 + (lt & 1) * 8 + lr) * F_A_LD + (lt >> 1) * 8) * 2;
    const unsigned bHb = sb + (F_BH + (wn * 32 + (lt >> 1) * 8 + lr) * LDAB + (lt & 1) * 8) * 2;
    const unsigned bLb = sb + (F_BL + (wn * 32 + (lt >> 1) * 8 + lr) * LDAB + (lt & 1) * 8) * 2;

    const float* encb = enc + (size_t)b * NN * EMB;
    const size_t outbase = ((size_t)(b * PP + p0)) * NN;

#pragma unroll 1
    for (int nc = 0; nc < 4; nc++) {
        float acc[4][4];
#pragma unroll
        for (int nt = 0; nt < 4; nt++)
#pragma unroll
            for (int e = 0; e < 4; e++) acc[nt][e] = 0.0f;

        float4 bv[4];
#pragma unroll
        for (int i = 0; i < 4; i++) {
            const int lin = tid + i * 256;
            const int row = lin >> 3, c4 = lin & 7;
            bv[i] = *(const float4*)&encb[(size_t)(nc * 128 + row) * 256 + c4 * 4];
        }

#pragma unroll 1
        for (int kb = 0; kb < 8; kb++) {
            const int bufo = (kb & 1) * F_BSTAGE;
            __nv_bfloat16* Bh = smf + bufo + F_BH;
            __nv_bfloat16* Bl = smf + bufo + F_BL;
#pragma unroll
            for (int i = 0; i < 4; i++) {
                const int lin = tid + i * 256;
                const int row = lin >> 3, c4 = lin & 7;
                store_hl4(&Bh[row * LDAB + c4 * 4], &Bl[row * LDAB + c4 * 4], bv[i]);
            }
            __syncthreads();

            if (kb < 7) {
                const int k0 = (kb + 1) * 32;
#pragma unroll
                for (int i = 0; i < 4; i++) {
                    const int lin = tid + i * 256;
                    const int row = lin >> 3, c4 = lin & 7;
                    bv[i] = *(const float4*)&encb[(size_t)(nc * 128 + row) * 256 + k0 + c4 * 4];
                }
            }

            const unsigned bo2 = bufo * 2;
#pragma unroll
            for (int ks = 0; ks < 32; ks += 16) {
                const int ka = kb * 32 + ks;
                unsigned ah[4], al[4], bh[4][2], bl[4][2];
                ldsm_x4(ah[0], ah[1], ah[2], ah[3], aHb + ka * 2);
                ldsm_x4(al[0], al[1], al[2], al[3], aLb + ka * 2);
#pragma unroll
                for (int p = 0; p < 2; p++) {
                    ldsm_x4(bh[2 * p][0], bh[2 * p][1], bh[2 * p + 1][0], bh[2 * p + 1][1],
                            bHb + bo2 + (p * 16 * LDAB + ks) * 2);
                    ldsm_x4(bl[2 * p][0], bl[2 * p][1], bl[2 * p + 1][0], bl[2 * p + 1][1],
                            bLb + bo2 + (p * 16 * LDAB + ks) * 2);
                }
#pragma unroll
                for (int nt = 0; nt < 4; nt++) {
                    mma16816(acc[nt], ah, bh[nt]);
                    mma16816(acc[nt], ah, bl[nt]);
                    mma16816(acc[nt], al, bh[nt]);
                }
            }
        }

#pragma unroll
        for (int part = 0; part < 2; part++) {
            const int rloc = wm * 16 + gr + part * 8;
            const float tauf = s_tau[rloc];
            const size_t rowoff = outbase + (size_t)rloc * NN;
            float lsum = 0.0f;
#pragma unroll
            for (int nt = 0; nt < 4; nt++) {
                const int col = nc * 128 + wn * 32 + nt * 8 + 2 * qc;
                float2 d2 = *(const float2*)&dist[rowoff + col];
                float sc0 = acc[nt][part * 2] * 0.0625f
                          + ((d2.x <= tauf) ? (-d2.x * 0.7071067811865475f) : 1.0f);
                float sc1 = acc[nt][part * 2 + 1] * 0.0625f
                          + ((d2.y <= tauf) ? (-d2.y * 0.7071067811865475f) : 1.0f);
                float cc0 = -__fdividef(20.0f, __expf(2.0f * sc0) + 1.0f);
                float cc1 = -__fdividef(20.0f, __expf(2.0f * sc1) + 1.0f);
                if (anymask) {
                    float2 mk = *(const float2*)&mask[rowoff + col];
                    cc0 += mk.x; cc1 += mk.y;
                }
                const float e0 = __expf(cc0);
                const float e1 = __expf(cc1);
                lsum += e0 + e1;
                *(float2*)&out[rowoff + col] = make_float2(e0, e1);
            }
            atomicAdd(&s_sum[rloc], lsum);
        }
    }
    __syncthreads();

    if (tid < 32) s_sum[tid] = 1.0f / s_sum[tid];
    __syncthreads();

    float2* out2 = (float2*)&out[outbase];
#pragma unroll 4
    for (int i = tid; i < 32 * 256; i += 256) {
        const float inv = s_sum[i >> 8];
        float2 v = out2[i];
        v.x *= inv; v.y *= inv;
        out2[i] = v;
    }
}

// ---------------------------------------------------------------------------
// Launch
// ---------------------------------------------------------------------------
extern "C" void kernel_launch(void* const* d_in, const int* in_sizes, int n_in,
                              void* d_out, int out_size)
{
    const float* enc   = (const float*)d_in[0];
    const float* last  = (const float*)d_in[1];
    const float* load  = (const float*)d_in[2];
    const float* dist  = (const float*)d_in[3];
    const float* mask  = (const float*)d_in[6];
    const float* Wq    = (const float*)d_in[7];
    const float* Wk    = (const float*)d_in[8];
    const float* Wv    = (const float*)d_in[9];
    const float* Wc    = (const float*)d_in[10];
    const float* Wcb   = (const float*)d_in[11];
    float* out = (float*)d_out;

    init_flag_kernel<<<1, 32>>>();

    const size_t smP = (size_t)2 * P_STAGE * sizeof(__nv_bfloat16);  // 61440 B
    cudaFuncSetAttribute(proj_kernel,
                         cudaFuncAttributeMaxDynamicSharedMemorySize, (int)smP);
    proj_kernel<<<dim3(BB * PP / 128, 4, 3), 256, smP>>>(
        enc, last, load, Wk, Wv, Wq, mask);

    const size_t smA = (size_t)A6_TOT * sizeof(__nv_bfloat16);  // 82432 B
    cudaFuncSetAttribute(attention11_kernel,
                         cudaFuncAttributeMaxDynamicSharedMemorySize, (int)smA);
    dim3 gA(BB * HH, 1);  // 512 blocks, 4 p-tiles each
    attention11_kernel<<<gA, 256, smA>>>(mask);

    cudaFuncSetAttribute(gemm_wc_kernel,
                         cudaFuncAttributeMaxDynamicSharedMemorySize, (int)smP);
    gemm_wc_kernel<<<dim3(BB * PP / 128, 4), 256, smP>>>(Wc, Wcb);

    const size_t smF = (size_t)F_TOT * sizeof(__nv_bfloat16);  // 74752 B
    cudaFuncSetAttribute(final7_kernel,
                         cudaFuncAttributeMaxDynamicSharedMemorySize, (int)smF);
    dim3 gF(PP / 32, BB);
    final7_kernel<<<gF, 256, smF>>>(enc, dist, mask, out);
}

// round 17
// speedup vs baseline: 1.0525x; 1.0525x over previous
#include <cuda_runtime.h>
#include <cuda_bf16.h>
#include <math.h>

// ---------------------------------------------------------------------------
// Problem constants
// ---------------------------------------------------------------------------
#define BB  32
#define PP  512
#define NN  512
#define EMB 256
#define HH  16
#define DD  16

// Scratch (device globals -- no allocation allowed)
__device__ float g_K[BB * HH * NN * DD];    // [b][h][n][d]
__device__ float g_V[BB * HH * NN * DD];    // [b][h][n][d]
__device__ float g_Q[BB * HH * PP * DD];    // [b][h][p][d]
__device__ float g_att[BB * PP * HH * DD];  // [b][p][h*16+d]
__device__ float g_mh[BB * PP * EMB];       // [b][p][e]
__device__ int   g_mask_nz;                 // 1 if any ninf_mask bit set

// ---------------------------------------------------------------------------
// mma.sync m16n8k16 bf16 + ldmatrix helpers
// ---------------------------------------------------------------------------
__device__ __forceinline__ void mma16816(float* c, const unsigned* a, const unsigned* b) {
    asm volatile(
        "mma.sync.aligned.m16n8k16.row.col.f32.bf16.bf16.f32 "
        "{%0,%1,%2,%3}, {%4,%5,%6,%7}, {%8,%9}, {%0,%1,%2,%3};"
        : "+f"(c[0]), "+f"(c[1]), "+f"(c[2]), "+f"(c[3])
        : "r"(a[0]), "r"(a[1]), "r"(a[2]), "r"(a[3]), "r"(b[0]), "r"(b[1]));
}

__device__ __forceinline__ void ldsm_x4(unsigned& d0, unsigned& d1,
                                        unsigned& d2, unsigned& d3, unsigned addr) {
    asm volatile("ldmatrix.sync.aligned.m8n8.x4.shared.b16 {%0,%1,%2,%3}, [%4];"
                 : "=r"(d0), "=r"(d1), "=r"(d2), "=r"(d3) : "r"(addr));
}

__device__ __forceinline__ unsigned pack_bf16x2(float lo, float hi) {
    unsigned r;
    asm("cvt.rn.satfinite.bf16x2.f32 %0, %1, %2;" : "=r"(r) : "f"(hi), "f"(lo));
    return r;
}

__device__ __forceinline__ void pack_hl(float x0, float x1, unsigned& ph, unsigned& pl) {
    ph = pack_bf16x2(x0, x1);
    const float h0 = __uint_as_float(ph << 16);
    const float h1 = __uint_as_float(ph & 0xFFFF0000u);
    pl = pack_bf16x2(x0 - h0, x1 - h1);
}

__device__ __forceinline__ void cvt_hl(float x, __nv_bfloat16& h, __nv_bfloat16& l) {
    h = __float2bfloat16(x);
    l = __float2bfloat16(x - __bfloat162float(h));
}

__device__ __forceinline__ void store_hl4(__nv_bfloat16* p_h, __nv_bfloat16* p_l, float4 v) {
    unsigned h01, l01, h23, l23;
    pack_hl(v.x, v.y, h01, l01);
    pack_hl(v.z, v.w, h23, l23);
    *(unsigned*)(p_h)     = h01;
    *(unsigned*)(p_h + 2) = h23;
    *(unsigned*)(p_l)     = l01;
    *(unsigned*)(p_l + 2) = l23;
}

#define LDAB 40  // padded bf16 row stride (80 B) -> LDSM conflict-free

// Pipelined GEMM stage layout (elements)
#define P_AH   0
#define P_AL   (128 * LDAB)
#define P_BH   (256 * LDAB)
#define P_BL   (256 * LDAB + 64 * LDAB)
#define P_STAGE (384 * LDAB)   // 15360 elems = 30720 B per stage

// ---------------------------------------------------------------------------
// Flag init
// ---------------------------------------------------------------------------
__global__ void init_flag_kernel() {
    if (threadIdx.x == 0) g_mask_nz = 0;
}

// ---------------------------------------------------------------------------
// Merged projection kernel (pipelined, double-buffered smem).
// blockIdx.z selects K / V / Q; mask OR-scan spread over ALL blocks.
// ---------------------------------------------------------------------------
__global__ __launch_bounds__(256, 2) void proj_kernel(
    const float* __restrict__ enc,
    const float* __restrict__ last,
    const float* __restrict__ loadv,
    const float* __restrict__ Wk,
    const float* __restrict__ Wv,
    const float* __restrict__ Wq,
    const float* __restrict__ mask)
{
    extern __shared__ __nv_bfloat16 smp[];
    __shared__ unsigned sred[8];

    const int z = blockIdx.z;
    const float* Ap = (z == 2) ? last : enc;
    const float* W  = (z == 0) ? Wk : (z == 1) ? Wv : Wq;
    const int ldw   = (z == 2) ? 257 : 256;
    const bool extra = (z == 2);
    float* out = (z == 0) ? g_K : (z == 1) ? g_V : g_Q;

    const int m0 = blockIdx.x * 128;
    const int n0 = blockIdx.y * 64;
    const int tid = threadIdx.x;
    const int warp = tid >> 5, lane = tid & 31;
    const int wm = warp >> 1, wn = warp & 1;
    const int gr = lane >> 2, qc = lane & 3;
    const int lt = lane >> 3, lr = lane & 7;

    // ---- mask OR-scan (spread across all 1536 blocks) ----
    {
        unsigned accm = 0;
        const unsigned bid = blockIdx.z * 512u + blockIdx.y * 128u + blockIdx.x;
        const uint4* m4 = (const uint4*)mask;
        for (unsigned i = bid * 256u + tid; i < 2097152u; i += 1536u * 256u) {
            uint4 v = m4[i];
            accm |= v.x | v.y | v.z | v.w;
        }
#pragma unroll
        for (int o = 16; o; o >>= 1) accm |= __shfl_xor_sync(0xffffffffu, accm, o);
        if (lane == 0) sred[warp] = accm;
        __syncthreads();
        if (tid == 0) {
            unsigned a = 0;
#pragma unroll
            for (int i = 0; i < 8; i++) a |= sred[i];
            if (a) atomicOr(&g_mask_nz, 1);
        }
    }

    const unsigned sb = (unsigned)__cvta_generic_to_shared(smp);
    const unsigned aH0 = sb + (P_AH + (wm * 32 + (lt & 1) * 8 + lr) * LDAB + (lt >> 1) * 8) * 2;
    const unsigned aL0 = sb + (P_AL + (wm * 32 + (lt & 1) * 8 + lr) * LDAB + (lt >> 1) * 8) * 2;
    const unsigned bH0 = sb + (P_BH + (wn * 32 + (lt >> 1) * 8 + lr) * LDAB + (lt & 1) * 8) * 2;
    const unsigned bL0 = sb + (P_BL + (wn * 32 + (lt >> 1) * 8 + lr) * LDAB + (lt & 1) * 8) * 2;

    float acc[2][4][4];
#pragma unroll
    for (int mt = 0; mt < 2; mt++)
#pragma unroll
        for (int nt = 0; nt < 4; nt++)
#pragma unroll
            for (int e = 0; e < 4; e++) acc[mt][nt][e] = 0.0f;

    float4 av[4];
    float wv[2][4];
#pragma unroll
    for (int i = 0; i < 4; i++) {
        const int lin = tid + i * 256;
        const int row = lin >> 3, c4 = lin & 7;
        av[i] = *(const float4*)(Ap + (size_t)(m0 + row) * 256 + c4 * 4);
    }
#pragma unroll
    for (int i = 0; i < 2; i++) {
        const int lin = tid + i * 256;
        const int row = lin >> 3, c4 = lin & 7;
        const float* wp = W + (size_t)(n0 + row) * ldw + c4 * 4;
        if (extra) {
            wv[i][0] = wp[0]; wv[i][1] = wp[1]; wv[i][2] = wp[2]; wv[i][3] = wp[3];
        } else {
            float4 t = *(const float4*)wp;
            wv[i][0] = t.x; wv[i][1] = t.y; wv[i][2] = t.z; wv[i][3] = t.w;
        }
    }

#pragma unroll 1
    for (int kb = 0; kb < 8; kb++) {
        const int bufo = (kb & 1) * P_STAGE;
        __nv_bfloat16* Ah = smp + bufo + P_AH;
        __nv_bfloat16* Al = smp + bufo + P_AL;
        __nv_bfloat16* Bh = smp + bufo + P_BH;
        __nv_bfloat16* Bl = smp + bufo + P_BL;
#pragma unroll
        for (int i = 0; i < 4; i++) {
            const int lin = tid + i * 256;
            const int row = lin >> 3, c4 = lin & 7;
            store_hl4(&Ah[row * LDAB + c4 * 4], &Al[row * LDAB + c4 * 4], av[i]);
        }
#pragma unroll
        for (int i = 0; i < 2; i++) {
            const int lin = tid + i * 256;
            const int row = lin >> 3, c4 = lin & 7;
            float4 t = make_float4(wv[i][0], wv[i][1], wv[i][2], wv[i][3]);
            store_hl4(&Bh[row * LDAB + c4 * 4], &Bl[row * LDAB + c4 * 4], t);
        }
        __syncthreads();

        if (kb < 7) {
            const int k0 = (kb + 1) * 32;
#pragma unroll
            for (int i = 0; i < 4; i++) {
                const int lin = tid + i * 256;
                const int row = lin >> 3, c4 = lin & 7;
                av[i] = *(const float4*)(Ap + (size_t)(m0 + row) * 256 + k0 + c4 * 4);
            }
#pragma unroll
            for (int i = 0; i < 2; i++) {
                const int lin = tid + i * 256;
                const int row = lin >> 3, c4 = lin & 7;
                const float* wp = W + (size_t)(n0 + row) * ldw + k0 + c4 * 4;
                if (extra) {
                    wv[i][0] = wp[0]; wv[i][1] = wp[1]; wv[i][2] = wp[2]; wv[i][3] = wp[3];
                } else {
                    float4 t = *(const float4*)wp;
                    wv[i][0] = t.x; wv[i][1] = t.y; wv[i][2] = t.z; wv[i][3] = t.w;
                }
            }
        }

        const unsigned bo2 = bufo * 2;
#pragma unroll
        for (int ks = 0; ks < 32; ks += 16) {
            unsigned ah[2][4], al[2][4], bh[4][2], bl[4][2];
#pragma unroll
            for (int mt = 0; mt < 2; mt++) {
                ldsm_x4(ah[mt][0], ah[mt][1], ah[mt][2], ah[mt][3],
                        aH0 + bo2 + (mt * 16 * LDAB + ks) * 2);
                ldsm_x4(al[mt][0], al[mt][1], al[mt][2], al[mt][3],
                        aL0 + bo2 + (mt * 16 * LDAB + ks) * 2);
            }
#pragma unroll
            for (int p = 0; p < 2; p++) {
                ldsm_x4(bh[2 * p][0], bh[2 * p][1], bh[2 * p + 1][0], bh[2 * p + 1][1],
                        bH0 + bo2 + (p * 16 * LDAB + ks) * 2);
                ldsm_x4(bl[2 * p][0], bl[2 * p][1], bl[2 * p + 1][0], bl[2 * p + 1][1],
                        bL0 + bo2 + (p * 16 * LDAB + ks) * 2);
            }
#pragma unroll
            for (int mt = 0; mt < 2; mt++)
#pragma unroll
                for (int nt = 0; nt < 4; nt++) {
                    mma16816(acc[mt][nt], ah[mt], bh[nt]);
                    mma16816(acc[mt][nt], ah[mt], bl[nt]);
                    mma16816(acc[mt][nt], al[mt], bh[nt]);
                }
        }
    }

#pragma unroll
    for (int mt = 0; mt < 2; mt++) {
#pragma unroll
        for (int part = 0; part < 2; part++) {
            const int m = m0 + wm * 32 + mt * 16 + gr + part * 8;
            float ex = 0.0f;
            if (extra) ex = loadv[m];
#pragma unroll
            for (int nt = 0; nt < 4; nt++) {
                const int col = n0 + wn * 32 + nt * 8 + 2 * qc;
                float2 v = make_float2(acc[mt][nt][part * 2], acc[mt][nt][part * 2 + 1]);
                if (extra) {
                    v.x += ex * W[(size_t)col * ldw + 256];
                    v.y += ex * W[(size_t)(col + 1) * ldw + 256];
                }
                const int b = m >> 9, n = m & 511;
                const int h = col >> 4, d = col & 15;
                *(float2*)&out[(((size_t)(b * 16 + h) * 512) + n) * 16 + d] = v;
            }
        }
    }
}

// ---------------------------------------------------------------------------
// Wc projection (pipelined, double-buffered): g_att @ Wc^T + bias -> g_mh
// ---------------------------------------------------------------------------
__global__ __launch_bounds__(256, 2) void gemm_wc_kernel(
    const float* __restrict__ W,
    const float* __restrict__ bias)
{
    extern __shared__ __nv_bfloat16 smp[];
    const float* Ap = (const float*)g_att;
    float* out = g_mh;

    const int m0 = blockIdx.x * 128;
    const int n0 = blockIdx.y * 64;
    const int tid = threadIdx.x;
    const int warp = tid >> 5, lane = tid & 31;
    const int wm = warp >> 1, wn = warp & 1;
    const int gr = lane >> 2, qc = lane & 3;
    const int lt = lane >> 3, lr = lane & 7;

    const unsigned sb = (unsigned)__cvta_generic_to_shared(smp);
    const unsigned aH0 = sb + (P_AH + (wm * 32 + (lt & 1) * 8 + lr) * LDAB + (lt >> 1) * 8) * 2;
    const unsigned aL0 = sb + (P_AL + (wm * 32 + (lt & 1) * 8 + lr) * LDAB + (lt >> 1) * 8) * 2;
    const unsigned bH0 = sb + (P_BH + (wn * 32 + (lt >> 1) * 8 + lr) * LDAB + (lt & 1) * 8) * 2;
    const unsigned bL0 = sb + (P_BL + (wn * 32 + (lt >> 1) * 8 + lr) * LDAB + (lt & 1) * 8) * 2;

    float acc[2][4][4];
#pragma unroll
    for (int mt = 0; mt < 2; mt++)
#pragma unroll
        for (int nt = 0; nt < 4; nt++)
#pragma unroll
            for (int e = 0; e < 4; e++) acc[mt][nt][e] = 0.0f;

    float4 av[4], wv[2];
#pragma unroll
    for (int i = 0; i < 4; i++) {
        const int lin = tid + i * 256;
        const int row = lin >> 3, c4 = lin & 7;
        av[i] = *(const float4*)(Ap + (size_t)(m0 + row) * 256 + c4 * 4);
    }
#pragma unroll
    for (int i = 0; i < 2; i++) {
        const int lin = tid + i * 256;
        const int row = lin >> 3, c4 = lin & 7;
        wv[i] = *(const float4*)(W + (size_t)(n0 + row) * 256 + c4 * 4);
    }

#pragma unroll 1
    for (int kb = 0; kb < 8; kb++) {
        const int bufo = (kb & 1) * P_STAGE;
        __nv_bfloat16* Ah = smp + bufo + P_AH;
        __nv_bfloat16* Al = smp + bufo + P_AL;
        __nv_bfloat16* Bh = smp + bufo + P_BH;
        __nv_bfloat16* Bl = smp + bufo + P_BL;
#pragma unroll
        for (int i = 0; i < 4; i++) {
            const int lin = tid + i * 256;
            const int row = lin >> 3, c4 = lin & 7;
            store_hl4(&Ah[row * LDAB + c4 * 4], &Al[row * LDAB + c4 * 4], av[i]);
        }
#pragma unroll
        for (int i = 0; i < 2; i++) {
            const int lin = tid + i * 256;
            const int row = lin >> 3, c4 = lin & 7;
            store_hl4(&Bh[row * LDAB + c4 * 4], &Bl[row * LDAB + c4 * 4], wv[i]);
        }
        __syncthreads();

        if (kb < 7) {
            const int k0 = (kb + 1) * 32;
#pragma unroll
            for (int i = 0; i < 4; i++) {
                const int lin = tid + i * 256;
                const int row = lin >> 3, c4 = lin & 7;
                av[i] = *(const float4*)(Ap + (size_t)(m0 + row) * 256 + k0 + c4 * 4);
            }
#pragma unroll
            for (int i = 0; i < 2; i++) {
                const int lin = tid + i * 256;
                const int row = lin >> 3, c4 = lin & 7;
                wv[i] = *(const float4*)(W + (size_t)(n0 + row) * 256 + k0 + c4 * 4);
            }
        }

        const unsigned bo2 = bufo * 2;
#pragma unroll
        for (int ks = 0; ks < 32; ks += 16) {
            unsigned ah[2][4], al[2][4], bh[4][2], bl[4][2];
#pragma unroll
            for (int mt = 0; mt < 2; mt++) {
                ldsm_x4(ah[mt][0], ah[mt][1], ah[mt][2], ah[mt][3],
                        aH0 + bo2 + (mt * 16 * LDAB + ks) * 2);
                ldsm_x4(al[mt][0], al[mt][1], al[mt][2], al[mt][3],
                        aL0 + bo2 + (mt * 16 * LDAB + ks) * 2);
            }
#pragma unroll
            for (int p = 0; p < 2; p++) {
                ldsm_x4(bh[2 * p][0], bh[2 * p][1], bh[2 * p + 1][0], bh[2 * p + 1][1],
                        bH0 + bo2 + (p * 16 * LDAB + ks) * 2);
                ldsm_x4(bl[2 * p][0], bl[2 * p][1], bl[2 * p + 1][0], bl[2 * p + 1][1],
                        bL0 + bo2 + (p * 16 * LDAB + ks) * 2);
            }
#pragma unroll
            for (int mt = 0; mt < 2; mt++)
#pragma unroll
                for (int nt = 0; nt < 4; nt++) {
                    mma16816(acc[mt][nt], ah[mt], bh[nt]);
                    mma16816(acc[mt][nt], ah[mt], bl[nt]);
                    mma16816(acc[mt][nt], al[mt], bh[nt]);
                }
        }
    }

#pragma unroll
    for (int mt = 0; mt < 2; mt++) {
#pragma unroll
        for (int part = 0; part < 2; part++) {
            const int m = m0 + wm * 32 + mt * 16 + gr + part * 8;
#pragma unroll
            for (int nt = 0; nt < 4; nt++) {
                const int col = n0 + wn * 32 + nt * 8 + 2 * qc;
                float2 v = make_float2(acc[mt][nt][part * 2], acc[mt][nt][part * 2 + 1]);
                v.x += bias[col]; v.y += bias[col + 1];
                *(float2*)&out[(size_t)m * 256 + col] = v;
            }
        }
    }
}

// ---------------------------------------------------------------------------
// Flash attention v10 (R15 config): Q fragments direct from gmem, 2 p-tiles
// per block, LDSM K/V, mask-skip.
// ---------------------------------------------------------------------------
#define KH_LD 24
#define VT_LD 520
#define A6_KH   0
#define A6_KL   (512 * KH_LD)
#define A6_VTH  (2 * 512 * KH_LD)
#define A6_VTL  (A6_VTH + 16 * VT_LD)
#define A6_TOT  (A6_VTL + 16 * VT_LD)   // 41216 elems = 82432 B

__global__ __launch_bounds__(256, 2) void attention10_kernel(
    const float* __restrict__ mask)
{
    extern __shared__ __nv_bfloat16 smb[];
    __nv_bfloat16* Kh  = smb + A6_KH;
    __nv_bfloat16* Kl  = smb + A6_KL;
    __nv_bfloat16* Vth = smb + A6_VTH;
    __nv_bfloat16* Vtl = smb + A6_VTL;

    const int bh = blockIdx.x;
    const int b  = bh >> 4;
    const int h  = bh & 15;
    const int tid = threadIdx.x;
    const int anymask = g_mask_nz;

    const float4* Kg4 = (const float4*)(g_K + (size_t)bh * (NN * DD));
    for (int i = tid; i < 2048; i += 256) {
        float4 v = Kg4[i];
        const int row = i >> 2, dg = (i & 3) * 4;
        store_hl4(&Kh[row * KH_LD + dg], &Kl[row * KH_LD + dg], v);
    }
    const float4* Vg4 = (const float4*)(g_V + (size_t)bh * (NN * DD));
    for (int i = tid; i < 2048; i += 256) {
        float4 v = Vg4[i];
        const int n = i >> 2, dg = (i & 3) * 4;
        float x[4] = {v.x, v.y, v.z, v.w};
#pragma unroll
        for (int j = 0; j < 4; j++) {
            __nv_bfloat16 hh, ll;
            cvt_hl(x[j], hh, ll);
            Vth[(dg + j) * VT_LD + n] = hh;
            Vtl[(dg + j) * VT_LD + n] = ll;
        }
    }
    __syncthreads();

    const int warp = tid >> 5, lane = tid & 31;
    const int gr = lane >> 2, qc = lane & 3;
    const int lt = lane >> 3, lr = lane & 7;
    const int prow = warp * 16;

    const unsigned sb = (unsigned)__cvta_generic_to_shared(smb);
    const unsigned kBase = sb + ((lt < 2 ? A6_KH : A6_KL)
                                 + lr * KH_LD + (lt & 1) * 8) * 2;
    const unsigned vBase = sb + ((lt < 2 ? A6_VTH : A6_VTL)
                                 + lr * VT_LD + (lt & 1) * 8) * 2;

#pragma unroll 1
    for (int ip = 0; ip < 2; ip++) {
        const int p0 = blockIdx.y * 256 + ip * 128;

        unsigned qh[4], ql[4];
        {
            const float2* q0 = (const float2*)(g_Q + ((size_t)bh * PP + p0 + prow + gr) * DD);
            const float2* q1 = (const float2*)(g_Q + ((size_t)bh * PP + p0 + prow + gr + 8) * DD);
            float2 a = q0[qc], bq = q1[qc], cq = q0[qc + 4], d = q1[qc + 4];
            pack_hl(a.x * 0.25f,  a.y * 0.25f,  qh[0], ql[0]);
            pack_hl(bq.x * 0.25f, bq.y * 0.25f, qh[1], ql[1]);
            pack_hl(cq.x * 0.25f, cq.y * 0.25f, qh[2], ql[2]);
            pack_hl(d.x * 0.25f,  d.y * 0.25f,  qh[3], ql[3]);
        }

        float m0 = -1e30f, m1 = -1e30f, l0 = 0.0f, l1 = 0.0f;
        float O[2][4];
#pragma unroll
        for (int nd = 0; nd < 2; nd++)
#pragma unroll
            for (int e = 0; e < 4; e++) O[nd][e] = 0.0f;

        const size_t mrow0 = ((size_t)(b * PP + p0 + prow + gr)) * NN;
        const size_t mrow1 = ((size_t)(b * PP + p0 + prow + gr + 8)) * NN;

#pragma unroll 1
        for (int c = 0; c < 8; c++) {
            const int n0c = c * 64;

            float s[8][4];
#pragma unroll
            for (int nf = 0; nf < 8; nf++) {
                s[nf][0] = s[nf][1] = s[nf][2] = s[nf][3] = 0.0f;
                unsigned kbh[2], kbl[2];
                ldsm_x4(kbh[0], kbh[1], kbl[0], kbl[1],
                        kBase + (n0c + nf * 8) * (KH_LD * 2));
                mma16816(s[nf], qh, kbh);
                mma16816(s[nf], qh, kbl);
                mma16816(s[nf], ql, kbh);
            }

            if (anymask) {
#pragma unroll
                for (int nf = 0; nf < 8; nf++) {
                    const int ncol = n0c + nf * 8 + 2 * qc;
                    float2 mk0 = *(const float2*)&mask[mrow0 + ncol];
                    float2 mk1 = *(const float2*)&mask[mrow1 + ncol];
                    s[nf][0] += mk0.x; s[nf][1] += mk0.y;
                    s[nf][2] += mk1.x; s[nf][3] += mk1.y;
                }
            }

            float mx0 = -1e30f, mx1 = -1e30f;
#pragma unroll
            for (int nf = 0; nf < 8; nf++) {
                mx0 = fmaxf(mx0, fmaxf(s[nf][0], s[nf][1]));
                mx1 = fmaxf(mx1, fmaxf(s[nf][2], s[nf][3]));
            }
            mx0 = fmaxf(mx0, __shfl_xor_sync(0xffffffffu, mx0, 1));
            mx0 = fmaxf(mx0, __shfl_xor_sync(0xffffffffu, mx0, 2));
            mx1 = fmaxf(mx1, __shfl_xor_sync(0xffffffffu, mx1, 1));
            mx1 = fmaxf(mx1, __shfl_xor_sync(0xffffffffu, mx1, 2));

            const float mn0 = fmaxf(m0, mx0);
            const float mn1 = fmaxf(m1, mx1);
            const float f0 = __expf(m0 - mn0);
            const float f1 = __expf(m1 - mn1);
            m0 = mn0; m1 = mn1;
#pragma unroll
            for (int nd = 0; nd < 2; nd++) {
                O[nd][0] *= f0; O[nd][1] *= f0;
                O[nd][2] *= f1; O[nd][3] *= f1;
            }

            float rs0 = 0.0f, rs1 = 0.0f;
#pragma unroll
            for (int nf = 0; nf < 8; nf++) {
                s[nf][0] = __expf(s[nf][0] - mn0);
                s[nf][1] = __expf(s[nf][1] - mn0);
                s[nf][2] = __expf(s[nf][2] - mn1);
                s[nf][3] = __expf(s[nf][3] - mn1);
                rs0 += s[nf][0] + s[nf][1];
                rs1 += s[nf][2] + s[nf][3];
            }
            rs0 += __shfl_xor_sync(0xffffffffu, rs0, 1);
            rs0 += __shfl_xor_sync(0xffffffffu, rs0, 2);
            rs1 += __shfl_xor_sync(0xffffffffu, rs1, 1);
            rs1 += __shfl_xor_sync(0xffffffffu, rs1, 2);
            l0 = l0 * f0 + rs0;
            l1 = l1 * f1 + rs1;

#pragma unroll
            for (int t = 0; t < 4; t++) {
                unsigned ah[4], al[4];
                pack_hl(s[2 * t][0],     s[2 * t][1],     ah[0], al[0]);
                pack_hl(s[2 * t][2],     s[2 * t][3],     ah[1], al[1]);
                pack_hl(s[2 * t + 1][0], s[2 * t + 1][1], ah[2], al[2]);
                pack_hl(s[2 * t + 1][2], s[2 * t + 1][3], ah[3], al[3]);
#pragma unroll
                for (int nd = 0; nd < 2; nd++) {
                    unsigned vbh[2], vbl[2];
                    ldsm_x4(vbh[0], vbh[1], vbl[0], vbl[1],
                            vBase + (nd * 8 * VT_LD + n0c + 16 * t) * 2);
                    mma16816(O[nd], ah, vbh);
                    mma16816(O[nd], ah, vbl);
                    mma16816(O[nd], al, vbh);
                }
            }
        }

        const float inv0 = 1.0f / l0;
        const float inv1 = 1.0f / l1;
        float* op0 = g_att + ((size_t)(b * PP + p0 + prow + gr)) * (HH * DD) + h * DD;
        float* op1 = g_att + ((size_t)(b * PP + p0 + prow + gr + 8)) * (HH * DD) + h * DD;
#pragma unroll
        for (int nd = 0; nd < 2; nd++) {
            *(float2*)&op0[nd * 8 + 2 * qc] = make_float2(O[nd][0] * inv0, O[nd][1] * inv0);
            *(float2*)&op1[nd * 8 + 2 * qc] = make_float2(O[nd][2] * inv1, O[nd][3] * inv1);
        }
    }
}

// ---------------------------------------------------------------------------
// Final fused kernel v8: 64-row p-tiles (256 blocks = one wave; enc staging
// halved). 8 warps as 4m x 2n; nc = 8 chunks of 64 cols; acc[4][4].
// tau-first (2-way interleave), B k-pipelined, fixed shift 10, rescale.
// ---------------------------------------------------------------------------
#define F8_BH 0
#define F8_BL (64 * LDAB)
#define F8_BSTAGE (128 * LDAB)              // 5120 elems per stage
#define F8_AH (2 * F8_BSTAGE)               // 10240
#define F8_A_LD 264
#define F8_AL (F8_AH + 64 * F8_A_LD)
#define F8_TOT (F8_AL + 64 * F8_A_LD)       // 44032 elems = 88064 B

__global__ __launch_bounds__(256, 2) void final8_kernel(
    const float* __restrict__ enc,
    const float* __restrict__ dist,
    const float* __restrict__ mask,
    float* __restrict__ out)
{
    extern __shared__ __nv_bfloat16 smf[];
    __shared__ float s_tau[64];
    __shared__ float s_sum[64];

    const int b = blockIdx.y;
    const int p0 = blockIdx.x * 64;
    const int tid = threadIdx.x;
    const int warp = tid >> 5, lane = tid & 31;
    const int wm = warp >> 1, wn = warp & 1;   // 4m x 2n
    const int gr = lane >> 2, qc = lane & 3;
    const int lt = lane >> 3, lr = lane & 7;
    const int anymask = g_mask_nz;

    if (tid < 64) s_sum[tid] = 0.0f;

    // ---- phase A: per-row tau, 8 rows per warp, 2-way interleaved ----
#pragma unroll 1
    for (int rp = 0; rp < 4; rp++) {
        const int r0 = warp * 8 + rp * 2;
        unsigned key[2][16];
#pragma unroll
        for (int rr = 0; rr < 2; rr++) {
            const float* drow = dist + ((size_t)(b * PP + p0 + r0 + rr)) * NN;
#pragma unroll
            for (int j = 0; j < 16; j++) {
                unsigned u = __float_as_uint(drow[j * 32 + lane]);
                key[rr][j] = (u & 0x80000000u) ? ~u : (u ^ 0x80000000u);
            }
        }
        unsigned lo[2] = {0u, 0u}, hi[2] = {0xffffffffu, 0xffffffffu};
#pragma unroll 1
        for (int it = 0; it < 32; it++) {
            unsigned mid[2]; int c[2];
#pragma unroll
            for (int rr = 0; rr < 2; rr++) {
                mid[rr] = lo[rr] + ((hi[rr] - lo[rr]) >> 1);
                int cc = 0;
#pragma unroll
                for (int j = 0; j < 16; j++) cc += (key[rr][j] <= mid[rr]) ? 1 : 0;
                c[rr] = cc;
            }
            c[0] = __reduce_add_sync(0xffffffffu, c[0]);
            c[1] = __reduce_add_sync(0xffffffffu, c[1]);
#pragma unroll
            for (int rr = 0; rr < 2; rr++) {
                if (c[rr] >= 100) hi[rr] = mid[rr]; else lo[rr] = mid[rr] + 1;
            }
        }
        if (lane == 0) {
#pragma unroll
            for (int rr = 0; rr < 2; rr++) {
                const unsigned tau = hi[rr];
                const unsigned u = (tau & 0x80000000u) ? (tau ^ 0x80000000u) : ~tau;
                s_tau[r0 + rr] = __uint_as_float(u);
            }
        }
    }

    // ---- stage A (mh tile, 64 rows FULL K) once ----
    __nv_bfloat16* Ah = smf + F8_AH;
    __nv_bfloat16* Al = smf + F8_AL;
#pragma unroll
    for (int i = 0; i < 16; i++) {
        const int lin = tid + i * 256;
        const int row = lin >> 6, c4 = lin & 63;
        float4 av = *(const float4*)&g_mh[((size_t)(b * PP + p0 + row)) * 256 + c4 * 4];
        store_hl4(&Ah[row * F8_A_LD + c4 * 4], &Al[row * F8_A_LD + c4 * 4], av);
    }
    __syncthreads();

    const unsigned sb = (unsigned)__cvta_generic_to_shared(smf);
    const unsigned aHb = sb + (F8_AH + (wm * 16 + (lt & 1) * 8 + lr) * F8_A_LD + (lt >> 1) * 8) * 2;
    const unsigned aLb = sb + (F8_AL + (wm * 16 + (lt & 1) * 8 + lr) * F8_A_LD + (lt >> 1) * 8) * 2;
    const unsigned bHb = sb + (F8_BH + (wn * 32 + (lt >> 1) * 8 + lr) * LDAB + (lt & 1) * 8) * 2;
    const unsigned bLb = sb + (F8_BL + (wn * 32 + (lt >> 1) * 8 + lr) * LDAB + (lt & 1) * 8) * 2;

    const float* encb = enc + (size_t)b * NN * EMB;
    const size_t outbase = ((size_t)(b * PP + p0)) * NN;

#pragma unroll 1
    for (int nc = 0; nc < 8; nc++) {
        float acc[4][4];
#pragma unroll
        for (int nt = 0; nt < 4; nt++)
#pragma unroll
            for (int e = 0; e < 4; e++) acc[nt][e] = 0.0f;

        // prologue B loads (64 rows x 32 k = 512 float4, 2 per thread)
        float4 bv[2];
#pragma unroll
        for (int i = 0; i < 2; i++) {
            const int lin = tid + i * 256;
            const int row = lin >> 3, c4 = lin & 7;
            bv[i] = *(const float4*)&encb[(size_t)(nc * 64 + row) * 256 + c4 * 4];
        }

#pragma unroll 1
        for (int kb = 0; kb < 8; kb++) {
            const int bufo = (kb & 1) * F8_BSTAGE;
            __nv_bfloat16* Bh = smf + bufo + F8_BH;
            __nv_bfloat16* Bl = smf + bufo + F8_BL;
#pragma unroll
            for (int i = 0; i < 2; i++) {
                const int lin = tid + i * 256;
                const int row = lin >> 3, c4 = lin & 7;
                store_hl4(&Bh[row * LDAB + c4 * 4], &Bl[row * LDAB + c4 * 4], bv[i]);
            }
            __syncthreads();

            if (kb < 7) {
                const int k0 = (kb + 1) * 32;
#pragma unroll
                for (int i = 0; i < 2; i++) {
                    const int lin = tid + i * 256;
                    const int row = lin >> 3, c4 = lin & 7;
                    bv[i] = *(const float4*)&encb[(size_t)(nc * 64 + row) * 256 + k0 + c4 * 4];
                }
            }

            const unsigned bo2 = bufo * 2;
#pragma unroll
            for (int ks = 0; ks < 32; ks += 16) {
                const int ka = kb * 32 + ks;
                unsigned ah[4], al[4], bh[4][2], bl[4][2];
                ldsm_x4(ah[0], ah[1], ah[2], ah[3], aHb + ka * 2);
                ldsm_x4(al[0], al[1], al[2], al[3], aLb + ka * 2);
#pragma unroll
                for (int p = 0; p < 2; p++) {
                    ldsm_x4(bh[2 * p][0], bh[2 * p][1], bh[2 * p + 1][0], bh[2 * p + 1][1],
                            bHb + bo2 + (p * 16 * LDAB + ks) * 2);
                    ldsm_x4(bl[2 * p][0], bl[2 * p][1], bl[2 * p + 1][0], bl[2 * p + 1][1],
                            bLb + bo2 + (p * 16 * LDAB + ks) * 2);
                }
#pragma unroll
                for (int nt = 0; nt < 4; nt++) {
                    mma16816(acc[nt], ah, bh[nt]);
                    mma16816(acc[nt], ah, bl[nt]);
                    mma16816(acc[nt], al, bh[nt]);
                }
            }
        }

        // ---- epilogue for this nc: penalty + tanh-clip + exp(cc-10) ----
#pragma unroll
        for (int part = 0; part < 2; part++) {
            const int rloc = wm * 16 + gr + part * 8;
            const float tauf = s_tau[rloc];
            const size_t rowoff = outbase + (size_t)rloc * NN;
            float lsum = 0.0f;
#pragma unroll
            for (int nt = 0; nt < 4; nt++) {
                const int col = nc * 64 + wn * 32 + nt * 8 + 2 * qc;
                float2 d2 = *(const float2*)&dist[rowoff + col];
                float sc0 = acc[nt][part * 2] * 0.0625f
                          + ((d2.x <= tauf) ? (-d2.x * 0.7071067811865475f) : 1.0f);
                float sc1 = acc[nt][part * 2 + 1] * 0.0625f
                          + ((d2.y <= tauf) ? (-d2.y * 0.7071067811865475f) : 1.0f);
                float cc0 = -__fdividef(20.0f, __expf(2.0f * sc0) + 1.0f);
                float cc1 = -__fdividef(20.0f, __expf(2.0f * sc1) + 1.0f);
                if (anymask) {
                    float2 mk = *(const float2*)&mask[rowoff + col];
                    cc0 += mk.x; cc1 += mk.y;
                }
                const float e0 = __expf(cc0);
                const float e1 = __expf(cc1);
                lsum += e0 + e1;
                *(float2*)&out[rowoff + col] = make_float2(e0, e1);
            }
            atomicAdd(&s_sum[rloc], lsum);
        }
    }
    __syncthreads();

    if (tid < 64) s_sum[tid] = 1.0f / s_sum[tid];
    __syncthreads();

    // ---- rescale pass (L2-resident) ----
    float2* out2 = (float2*)&out[outbase];
#pragma unroll 4
    for (int i = tid; i < 64 * 256; i += 256) {
        const float inv = s_sum[i >> 8];
        float2 v = out2[i];
        v.x *= inv; v.y *= inv;
        out2[i] = v;
    }
}

// ---------------------------------------------------------------------------
// Launch
// ---------------------------------------------------------------------------
extern "C" void kernel_launch(void* const* d_in, const int* in_sizes, int n_in,
                              void* d_out, int out_size)
{
    const float* enc   = (const float*)d_in[0];
    const float* last  = (const float*)d_in[1];
    const float* load  = (const float*)d_in[2];
    const float* dist  = (const float*)d_in[3];
    const float* mask  = (const float*)d_in[6];
    const float* Wq    = (const float*)d_in[7];
    const float* Wk    = (const float*)d_in[8];
    const float* Wv    = (const float*)d_in[9];
    const float* Wc    = (const float*)d_in[10];
    const float* Wcb   = (const float*)d_in[11];
    float* out = (float*)d_out;

    init_flag_kernel<<<1, 32>>>();

    const size_t smP = (size_t)2 * P_STAGE * sizeof(__nv_bfloat16);  // 61440 B
    cudaFuncSetAttribute(proj_kernel,
                         cudaFuncAttributeMaxDynamicSharedMemorySize, (int)smP);
    proj_kernel<<<dim3(BB * PP / 128, 4, 3), 256, smP>>>(
        enc, last, load, Wk, Wv, Wq, mask);

    const size_t smA = (size_t)A6_TOT * sizeof(__nv_bfloat16);  // 82432 B
    cudaFuncSetAttribute(attention10_kernel,
                         cudaFuncAttributeMaxDynamicSharedMemorySize, (int)smA);
    dim3 gA(BB * HH, 2);  // 1024 blocks (R15 config)
    attention10_kernel<<<gA, 256, smA>>>(mask);

    cudaFuncSetAttribute(gemm_wc_kernel,
                         cudaFuncAttributeMaxDynamicSharedMemorySize, (int)smP);
    gemm_wc_kernel<<<dim3(BB * PP / 128, 4), 256, smP>>>(Wc, Wcb);

    const size_t smF = (size_t)F8_TOT * sizeof(__nv_bfloat16);  // 88064 B
    cudaFuncSetAttribute(final8_kernel,
                         cudaFuncAttributeMaxDynamicSharedMemorySize, (int)smF);
    dim3 gF(PP / 64, BB);  // 8 x 32 = 256 blocks (one wave)
    final8_kernel<<<gF, 256, smF>>>(enc, dist, mask, out);
}